// round 9
// baseline (speedup 1.0000x reference)
#include <cuda_runtime.h>
#include <cuda_bf16.h>
#include <cstdint>

// Problem dims (fixed by reference)
#define NB   4096
#define TT   2
#define LL   3
#define DIN  768
#define DSAE 16384
#define KSEL 64
#define KD   (LL*DIN)      // 2304
#define OD   (TT*LL*DIN)   // 4608

// Does this compilation pass have sm_103a/f features (tcgen05)?
#if defined(__CUDA_ARCH__) && (__CUDA_ARCH__ == 1030) && \
    (defined(__CUDA_ARCH_FEAT_SM103_ALL) || defined(__CUDA_ARCH_SPECIFIC__) || defined(__CUDA_ARCH_FAMILY_SPECIFIC__))
#define HAS_TC 1
#else
#define HAS_TC 0
#endif

// ---------------- scratch (static device memory; no allocations) ----------------
__device__ float g_Xr[(size_t)NB*KD];          // fp32 t-reduced x (for refinement)
__device__ __nv_bfloat16 g_Ahi[(size_t)NB*KD];
__device__ __nv_bfloat16 g_Alo[(size_t)NB*KD];
__device__ __nv_bfloat16 g_Bhi[(size_t)DSAE*KD];
__device__ __nv_bfloat16 g_Blo[(size_t)DSAE*KD];
__device__ int   g_tidx[NB*KSEL];
__device__ float g_tval[NB*KSEL];
__device__ float g_lpart[NB];

// ---------------- helpers ----------------
__device__ __forceinline__ uint32_t smem_u32(const void* p) {
    uint32_t a;
    asm("{ .reg .u64 t; cvta.to.shared.u64 t, %1; cvt.u32.u64 %0, t; }" : "=r"(a) : "l"(p));
    return a;
}
__device__ __forceinline__ uint32_t sw128(uint32_t o) { return o ^ ((o >> 3) & 0x70); }
__device__ __forceinline__ void cp16(uint32_t dst, const void* src) {
    asm volatile("cp.async.cg.shared.global [%0], [%1], 16;" :: "r"(dst), "l"(src));
}
__device__ __forceinline__ void split2(float v, unsigned short& h, unsigned short& l) {
    __nv_bfloat16 hb = __float2bfloat16(v);
    __nv_bfloat16 lb = __float2bfloat16(v - __bfloat162float(hb));
    h = *(unsigned short*)&hb; l = *(unsigned short*)&lb;
}
__device__ __forceinline__ int elect_one() {
    uint32_t pred;
    asm volatile("{\n\t.reg .pred p;\n\telect.sync _|p, 0xFFFFFFFF;\n\tselp.b32 %0, 1, 0, p;\n\t}" : "=r"(pred));
    return (int)pred;
}
__device__ __forceinline__ void mbar_init(uint32_t a, uint32_t cnt) {
    asm volatile("mbarrier.init.shared.b64 [%0], %1;" :: "r"(a), "r"(cnt) : "memory");
}
__device__ __forceinline__ void mbar_wait(uint32_t a, uint32_t parity) {
    asm volatile(
        "{\n\t.reg .pred P;\n"
        "WL_%=:\n\t"
        "mbarrier.try_wait.parity.acquire.cta.shared::cta.b64 P, [%0], %1, 0x989680;\n\t"
        "@P bra WD_%=;\n\t"
        "bra WL_%=;\n"
        "WD_%=:\n\t}"
        :: "r"(a), "r"(parity) : "memory");
}
__device__ __forceinline__ uint32_t cluster_rank() {
    uint32_t r;
    asm("mov.u32 %0, %%cluster_ctarank;" : "=r"(r));
    return r;
}
// mma.sync fallback primitives (plain sm_80+ PTX)
__device__ __forceinline__ void ldsm4(uint32_t* r, uint32_t addr) {
    asm volatile("ldmatrix.sync.aligned.m8n8.x4.shared.b16 {%0,%1,%2,%3}, [%4];"
        : "=r"(r[0]), "=r"(r[1]), "=r"(r[2]), "=r"(r[3]) : "r"(addr));
}
__device__ __forceinline__ void mma16816(float* c, const uint32_t* a, const uint32_t* b) {
    asm volatile("mma.sync.aligned.m16n8k16.row.col.f32.bf16.bf16.f32 "
        "{%0,%1,%2,%3}, {%4,%5,%6,%7}, {%8,%9}, {%0,%1,%2,%3};"
        : "+f"(c[0]), "+f"(c[1]), "+f"(c[2]), "+f"(c[3])
        : "r"(a[0]), "r"(a[1]), "r"(a[2]), "r"(a[3]), "r"(b[0]), "r"(b[1]));
}

#define NSTAGES 72                 // 72 chunks of k=32, all 4 planes per stage
#if HAS_TC
#define STAGE_BYTES 32768          // per-CTA: A-half 16KB + B-half 16KB
#else
#define STAGE_BYTES 49152          // A 16KB (128 rows) + B 32KB (256 rows)
#endif
#define GEMM_SMEM_HOST (3 * 49152 + 128)

// ---------------- kernel 1: fused t-reduce + fp32 save + 2-way bf16 split of A ----
__global__ void convertA_kernel(const float* __restrict__ x) {
    int i = blockIdx.x * blockDim.x + threadIdx.x;   // float4 index over [4096, 576]
    if (i >= NB * (KD / 4)) return;
    int b = i / (KD / 4), r = i - b * (KD / 4);
    const float4* x4 = (const float4*)x;
    float4 a = x4[(size_t)b * (OD / 4) + r];
    float4 c = x4[(size_t)b * (OD / 4) + (KD / 4) + r];
    float v[4] = {a.x + c.x, a.y + c.y, a.z + c.z, a.w + c.w};
    ((float4*)g_Xr)[i] = make_float4(v[0], v[1], v[2], v[3]);
    unsigned short h[4], l[4];
#pragma unroll
    for (int j = 0; j < 4; j++) split2(v[j], h[j], l[j]);
    ((uint2*)g_Ahi)[i] = make_uint2((unsigned)h[0] | ((unsigned)h[1] << 16), (unsigned)h[2] | ((unsigned)h[3] << 16));
    ((uint2*)g_Alo)[i] = make_uint2((unsigned)l[0] | ((unsigned)l[1] << 16), (unsigned)l[2] | ((unsigned)l[3] << 16));
}

// ---------------- kernel 2: W_enc transpose [K,N]->[N,K] + 2-way bf16 split -------
__global__ void convertB_kernel(const float* __restrict__ W) {
    __shared__ float ts[32][33];
    const int k0 = blockIdx.x * 32, n0 = blockIdx.y * 32;
    const int tx = threadIdx.x, ty = threadIdx.y;    // (32, 8)
#pragma unroll
    for (int j = 0; j < 4; j++)
        ts[ty + 8 * j][tx] = W[(size_t)(k0 + ty + 8 * j) * DSAE + n0 + tx];
    __syncthreads();
#pragma unroll
    for (int j = 0; j < 4; j++) {
        int nr = ty + 8 * j;
        float v = ts[tx][nr];
        unsigned short h, l;
        split2(v, h, l);
        size_t o = (size_t)(n0 + nr) * KD + k0 + tx;
        ((unsigned short*)g_Bhi)[o] = h;
        ((unsigned short*)g_Blo)[o] = l;
    }
}

// ---------------- kernel 3: encoder GEMM (cg2 tcgen05 if available, else mma.sync)
// C[4096,16384] fp32, split-bf16 3-term. Pair tile 256x256 (cg2), 512 thr/CTA.
// Stage = K32 chunk with all 4 planes; rows are [hi k0..31 | lo k0..31] (128B).
__global__ __launch_bounds__(512, 1) __cluster_dims__(2, 1, 1)
void enc_gemm_kernel(const float* __restrict__ bias, float* __restrict__ C)
{
    extern __shared__ char smem[];
    const uint32_t sbase = smem_u32(smem);
    const int tid = threadIdx.x, wid = tid >> 5, lid = tid & 31;

#if HAS_TC
    // ========== tcgen05 cg2 path: pair computes 256x256, M split 128/128 =========
    const uint32_t rank = cluster_rank();
    const int bm = (blockIdx.x >> 1) * 256;
    const int bn = blockIdx.y * 256;
    const int am = bm + (int)rank * 128;      // this CTA's A rows
    const int bnn = bn + (int)rank * 128;     // this CTA's B rows (N-half)

    const uint32_t mbar0 = sbase + 3 * STAGE_BYTES;   // full[3] @ +0, free[3] @ +24
    const uint32_t tptr  = mbar0 + 48;
    if (tid == 0) {
#pragma unroll
        for (int i = 0; i < 3; i++) {
            mbar_init(mbar0 + 8u * i, rank == 0 ? 513 : 512);  // full
            mbar_init(mbar0 + 24 + 8u * i, 1);                 // free (multicast commit)
        }
    }
    if (wid == 0) {
        asm volatile("tcgen05.alloc.cta_group::2.sync.aligned.shared::cta.b32 [%0], %1;"
                     :: "r"(tptr), "r"(256u) : "memory");
    }
    __syncthreads();
    uint32_t tmem;
    asm volatile("ld.shared.b32 %0, [%1];" : "=r"(tmem) : "r"(tptr));

    // all mbarriers initialized cluster-wide before any remote arrive / multicast
    asm volatile("barrier.cluster.arrive.aligned;" ::: "memory");
    asm volatile("barrier.cluster.wait.aligned;" ::: "memory");

    // idesc: f32 acc, bf16 x bf16, N=256, M=256 (cg2)
    const uint32_t idesc = (1u << 4) | (1u << 7) | (1u << 10) | ((256u / 8u) << 17) | ((256u / 16u) << 24);
    static __device__ constexpr uint64_t DESC_BASE =
        (uint64_t(2) << 61) | (uint64_t(1) << 46) | (uint64_t(64) << 32) | (uint64_t(1) << 16);
    const int paoff[3] = {0, 4, 0};   // Ahi, Alo, Ahi   (64B = 4 desc units)
    const int pboff[3] = {0, 0, 4};   // Bhi, Bhi, Blo

    auto produce = [&](int w) {
        const int kin = w * 32;
        const uint32_t sb = sbase + (uint32_t)(w % 3) * STAGE_BYTES;
#pragma unroll
        for (int i2 = 0; i2 < 2; i2++) {             // A-half: 128 rows x (hi|lo)
            int q = tid + 512 * i2;
            int row = q >> 3, sub = q & 7;
            int p = sub >> 2, c = sub & 3;
            const __nv_bfloat16* Ap = p ? g_Alo : g_Ahi;
            cp16(sb + sw128((uint32_t)((row << 7) | (p << 6) | (c << 4))),
                 Ap + (size_t)(am + row) * KD + kin + c * 8);
        }
#pragma unroll
        for (int i2 = 0; i2 < 2; i2++) {             // B-half: 128 rows x (hi|lo)
            int q = tid + 512 * i2;
            int row = q >> 3, sub = q & 7;
            int p = sub >> 2, c = sub & 3;
            const __nv_bfloat16* Bp = p ? g_Blo : g_Bhi;
            cp16(sb + 16384u + sw128((uint32_t)((row << 7) | (p << 6) | (c << 4))),
                 Bp + (size_t)(bnn + row) * KD + kin + c * 8);
        }
        asm volatile("cp.async.mbarrier.arrive.noinc.shared::cta.b64 [%0];"
                     :: "r"(mbar0 + 8u * (uint32_t)(w % 3)) : "memory");
    };

    // prologue: fill all 3 buffers
    produce(0); produce(1); produce(2);

    for (int s = 0; s < NSTAGES; s++) {
        const int buf = s % 3;
        const uint32_t fullb = mbar0 + 8u * (uint32_t)buf;
        const uint32_t freeb = mbar0 + 24u + 8u * (uint32_t)buf;
        const int u = s / 3;

        if (rank == 0) {
            // leader: wait both CTAs' loads (512 local + 1 forwarded), issue cg2 MMAs
            if (wid == 0 && elect_one()) {
                mbar_wait(fullb, (uint32_t)(u & 1));
                asm volatile("fence.proxy.async;" ::: "memory");
                const uint32_t sb = sbase + (uint32_t)buf * STAGE_BYTES;
                uint64_t ad = DESC_BASE | ((uint64_t)(sb >> 4) & 0x3FFF);
                uint64_t bd = DESC_BASE | ((uint64_t)((sb + 16384u) >> 4) & 0x3FFF);
#pragma unroll
                for (int combo = 0; combo < 3; combo++) {
#pragma unroll
                    for (int ks = 0; ks < 2; ks++) {
                        uint32_t en = ((s > 0) || (combo > 0) || (ks > 0)) ? 1u : 0u;
                        asm volatile(
                            "{\n\t.reg .pred p;\n\t"
                            "setp.ne.u32 p, %4, 0;\n\t"
                            "tcgen05.mma.cta_group::2.kind::f16 [%0], %1, %2, %3, "
                            "{%5, %5, %5, %5, %5, %5, %5, %5}, p;\n\t}"
                            :: "r"(tmem), "l"(ad + paoff[combo] + ks * 2),
                               "l"(bd + pboff[combo] + ks * 2), "r"(idesc), "r"(en), "r"(0u)
                            : "memory");
                    }
                }
                asm volatile(
                    "tcgen05.commit.cta_group::2.mbarrier::arrive::one.shared::cluster.multicast::cluster.b64 [%0], %1;"
                    :: "r"(freeb), "h"((unsigned short)3) : "memory");
            }
        } else {
            // follower: once local loads land, make them async-proxy visible and
            // forward one arrival to the leader's full barrier
            if (wid == 0 && elect_one()) {
                mbar_wait(fullb, (uint32_t)(u & 1));
                asm volatile("fence.proxy.async;" ::: "memory");
                asm volatile(
                    "{\n\t.reg .b32 ra;\n\t"
                    "mapa.shared::cluster.u32 ra, %0, %1;\n\t"
                    "mbarrier.arrive.shared::cluster.b64 _, [ra];\n\t}"
                    :: "r"(fullb), "r"(0u) : "memory");
            }
        }

        // produce stage s+3 into the buffer freed by stage s's MMA completion
        const int w = s + 3;
        if (w < NSTAGES) {
            mbar_wait(freeb, (uint32_t)(((w / 3) - 1) & 1));
            produce(w);
        }
    }

    // drain: last multicast commit to each free barrier -> phase 23 -> parity 1
    mbar_wait(mbar0 + 24u, 1u);
    mbar_wait(mbar0 + 32u, 1u);
    mbar_wait(mbar0 + 40u, 1u);
    asm volatile("tcgen05.fence::after_thread_sync;" ::: "memory");
    __syncthreads();

    // epilogue: each CTA reads its own TMEM half (128 lanes x 256 cols)
    {
        const int sp = wid & 3, cblk = wid >> 2;      // cblk in 0..3 -> 64 cols each
        const int m = sp * 32 + lid;
        const size_t crow = (size_t)(am + m) * DSAE + bn + cblk * 64;
#pragma unroll
        for (int cb = 0; cb < 64; cb += 32) {
            uint32_t r[32];
            asm volatile(
                "tcgen05.ld.sync.aligned.32x32b.x32.b32 "
                "{%0, %1, %2, %3, %4, %5, %6, %7, %8, %9, %10, %11, %12, %13, %14, %15, "
                "%16, %17, %18, %19, %20, %21, %22, %23, %24, %25, %26, %27, %28, %29, %30, %31}, [%32];"
                : "=r"(r[0]), "=r"(r[1]), "=r"(r[2]), "=r"(r[3]), "=r"(r[4]), "=r"(r[5]), "=r"(r[6]), "=r"(r[7]),
                  "=r"(r[8]), "=r"(r[9]), "=r"(r[10]), "=r"(r[11]), "=r"(r[12]), "=r"(r[13]), "=r"(r[14]), "=r"(r[15]),
                  "=r"(r[16]), "=r"(r[17]), "=r"(r[18]), "=r"(r[19]), "=r"(r[20]), "=r"(r[21]), "=r"(r[22]), "=r"(r[23]),
                  "=r"(r[24]), "=r"(r[25]), "=r"(r[26]), "=r"(r[27]), "=r"(r[28]), "=r"(r[29]), "=r"(r[30]), "=r"(r[31])
                : "r"(tmem + (uint32_t)(cblk * 64 + cb)));
            asm volatile("tcgen05.wait::ld.sync.aligned;" ::: "memory");
#pragma unroll
            for (int j = 0; j < 32; j++)
                C[crow + cb + j] = __uint_as_float(r[j]) + __ldg(&bias[bn + cblk * 64 + cb + j]);
        }
    }
    asm volatile("tcgen05.fence::before_thread_sync;" ::: "memory");
    __syncthreads();
    if (wid == 0) {
        asm volatile("tcgen05.relinquish_alloc_permit.cta_group::2.sync.aligned;" ::: "memory");
        asm volatile("tcgen05.dealloc.cta_group::2.sync.aligned.b32 %0, %1;" :: "r"(tmem), "r"(256u));
    }
    asm volatile("barrier.cluster.arrive.aligned;" ::: "memory");
    asm volatile("barrier.cluster.wait.aligned;" ::: "memory");
#else
    // ================= mma.sync fallback (plain sm_103) =================
    // Each CTA: 128x256 tile. 16 warps, warp tile 32x64.
    const int bme = blockIdx.x * 128;
    const int bn = blockIdx.y * 256;
    const int wm = (wid & 3) * 32;
    const int wn = (wid >> 2) * 64;

    float acc[2][8][4];
#pragma unroll
    for (int mi = 0; mi < 2; mi++)
#pragma unroll
        for (int j = 0; j < 8; j++)
#pragma unroll
            for (int e = 0; e < 4; e++) acc[mi][j][e] = 0.f;

    auto load_stage_f = [&](int w) {
        int kin = w * 32;
        uint32_t sb = sbase + (uint32_t)(w % 3) * STAGE_BYTES;
#pragma unroll
        for (int i2 = 0; i2 < 2; i2++) {        // A: 128 rows x (hi|lo)
            int q = tid + 512 * i2;
            int row = q >> 3, sub = q & 7;
            int p = sub >> 2, c = sub & 3;
            const __nv_bfloat16* Ap = p ? g_Alo : g_Ahi;
            cp16(sb + sw128((uint32_t)((row << 7) | (p << 6) | (c << 4))),
                 Ap + (size_t)(bme + row) * KD + kin + c * 8);
        }
#pragma unroll
        for (int i2 = 0; i2 < 4; i2++) {        // B: 256 rows x (hi|lo)
            int q = tid + 512 * i2;
            int row = q >> 3, sub = q & 7;
            int p = sub >> 2, c = sub & 3;
            const __nv_bfloat16* Bp = p ? g_Blo : g_Bhi;
            cp16(sb + 16384u + sw128((uint32_t)((row << 7) | (p << 6) | (c << 4))),
                 Bp + (size_t)(bn + row) * KD + kin + c * 8);
        }
        asm volatile("cp.async.commit_group;" ::: "memory");
    };

    load_stage_f(0);
    load_stage_f(1);

    for (int s = 0; s < NSTAGES; s++) {
        if (s + 2 < NSTAGES) {
            load_stage_f(s + 2);
            asm volatile("cp.async.wait_group 2;" ::: "memory");
        } else if (s == NSTAGES - 2) {
            asm volatile("cp.async.wait_group 1;" ::: "memory");
        } else {
            asm volatile("cp.async.wait_group 0;" ::: "memory");
        }
        __syncthreads();
        uint32_t ab = sbase + (uint32_t)(s % 3) * STAGE_BYTES;
        uint32_t bb = ab + 16384u;
        const int paoff[3] = {0, 64, 0};
        const int pboff[3] = {0, 0, 64};
#pragma unroll
        for (int combo = 0; combo < 3; combo++) {
#pragma unroll
            for (int ks = 0; ks < 2; ks++) {
                uint32_t a[2][4];
#pragma unroll
                for (int mi = 0; mi < 2; mi++) {
                    int row = wm + mi * 16 + (lid & 15);
                    uint32_t addr = ab + sw128((uint32_t)(row * 128 + paoff[combo] + ks * 32 + (lid >> 4) * 16));
                    ldsm4(a[mi], addr);
                }
                uint32_t bq[8][2];
#pragma unroll
                for (int nj = 0; nj < 4; nj++) {
                    int mat = lid >> 3, rin = lid & 7;
                    int n = wn + nj * 16 + ((mat >> 1) << 3) + rin;
                    int kb = pboff[combo] + ks * 32 + ((mat & 1) << 4);
                    uint32_t r4[4];
                    ldsm4(r4, bb + sw128((uint32_t)(n * 128 + kb)));
                    bq[nj * 2][0] = r4[0]; bq[nj * 2][1] = r4[1];
                    bq[nj * 2 + 1][0] = r4[2]; bq[nj * 2 + 1][1] = r4[3];
                }
#pragma unroll
                for (int mi = 0; mi < 2; mi++)
#pragma unroll
                    for (int j = 0; j < 8; j++) mma16816(acc[mi][j], a[mi], bq[j]);
            }
        }
        __syncthreads();
    }

#pragma unroll
    for (int mi = 0; mi < 2; mi++)
#pragma unroll
        for (int j = 0; j < 8; j++) {
            int col = bn + wn + j * 8 + (lid & 3) * 2;
            float b0v = __ldg(&bias[col]), b1v = __ldg(&bias[col + 1]);
            int r0 = bme + wm + mi * 16 + (lid >> 2);
            C[(size_t)r0 * DSAE + col]           = acc[mi][j][0] + b0v;
            C[(size_t)r0 * DSAE + col + 1]       = acc[mi][j][1] + b1v;
            C[(size_t)(r0 + 8) * DSAE + col]     = acc[mi][j][2] + b0v;
            C[(size_t)(r0 + 8) * DSAE + col + 1] = acc[mi][j][3] + b1v;
        }
#endif
}

// ---------------- kernel 4: TopK-64, register-resident + exact boundary refine ----
#define MARGIN 1e-3f
#define TPB 1024
#define VPT (DSAE / TPB)     // 16 values per thread
__global__ __launch_bounds__(TPB, 1) void topk_kernel(
    float* __restrict__ zbase,
    const float* __restrict__ Wenc,
    const float* __restrict__ bias)
{
    __shared__ int hist[4096];
    __shared__ int wsum[32];
    __shared__ float red[TPB];
    __shared__ int sh_B, sh_rem;
    __shared__ int n_hi, n_cand, out_cnt;
    __shared__ int   cand_idx[64];
    __shared__ float cand_val[64];
    __shared__ unsigned char cand_sel[64];

    const int b = blockIdx.x;
    const int tid = threadIdx.x;
    const int lane = tid & 31, warp = tid >> 5;
    float* row = zbase + (size_t)b * DSAE;

    unsigned ukey[VPT];
#pragma unroll
    for (int j = 0; j < VPT; j++) {
        unsigned u = __float_as_uint(row[tid + TPB * j]);
        ukey[j] = (u & 0x80000000u) ? ~u : (u | 0x80000000u);
    }

    int B1 = 0, target = KSEL;
#pragma unroll 1
    for (int pass = 0; pass < 2; pass++) {
#pragma unroll
        for (int i = tid; i < 4096; i += TPB) hist[i] = 0;
        __syncthreads();
#pragma unroll
        for (int j = 0; j < VPT; j++) {
            unsigned u = ukey[j];
            if (pass == 0) atomicAdd(&hist[u >> 20], 1);
            else if ((int)(u >> 20) == B1) atomicAdd(&hist[(u >> 8) & 0xFFFu], 1);
        }
        __syncthreads();
        int base = 4095 - 4 * tid;
        int s0 = hist[base] + hist[base - 1] + hist[base - 2] + hist[base - 3];
        int v = s0;
#pragma unroll
        for (int off = 1; off < 32; off <<= 1) {
            int n = __shfl_up_sync(0xffffffffu, v, off);
            if (lane >= off) v += n;
        }
        if (lane == 31) wsum[warp] = v;
        __syncthreads();
        if (warp == 0) {
            int t = wsum[lane];
#pragma unroll
            for (int off = 1; off < 32; off <<= 1) {
                int n = __shfl_up_sync(0xffffffffu, t, off);
                if (lane >= off) t += n;
            }
            wsum[lane] = t;
        }
        __syncthreads();
        int incl = v + (warp ? wsum[warp - 1] : 0);
        int excl = incl - s0;
        if (excl < target && target <= incl) {
            int rem = target - excl;
            for (int k = 0; k < 4; k++) {
                int bin = base - k;
                int c = hist[bin];
                if (c >= rem) { sh_B = bin; sh_rem = rem; break; }
                rem -= c;
            }
        }
        __syncthreads();
        if (pass == 0) { B1 = sh_B; target = sh_rem; }
        __syncthreads();
    }
    const unsigned P = ((unsigned)B1 << 12) | (unsigned)sh_B;

    auto unmap = [](unsigned u) {
        return __uint_as_float((u & 0x80000000u) ? (u & 0x7fffffffu) : ~u);
    };
    const float TL = unmap(P << 8);
    const float TH = unmap((P + 1) << 8);
    const float mlo = fminf(TL, TH) - MARGIN;
    const float mhi = fmaxf(TL, TH) + MARGIN;

    if (tid == 0) { n_hi = 0; n_cand = 0; out_cnt = 0; }
    __syncthreads();

#pragma unroll
    for (int j = 0; j < VPT; j++) {
        float v = unmap(ukey[j]);
        if (v > mhi) atomicAdd(&n_hi, 1);
        else if (v > mlo) {
            int e = atomicAdd(&n_cand, 1);
            if (e < 64) { cand_idx[e] = tid + TPB * j; cand_val[e] = v; }
        }
    }
    __syncthreads();
    const int slots = KSEL - n_hi;
    const int nc = (n_cand < 64) ? n_cand : 64;

    if (nc > slots) {
        for (int c = 0; c < nc; c++) {
            int s = cand_idx[c];
            float partial = 0.f;
            const float* xr = g_Xr + (size_t)b * KD;
            for (int k = tid; k < KD; k += TPB)
                partial += xr[k] * Wenc[(size_t)k * DSAE + s];
            red[tid] = partial;
            __syncthreads();
            for (int off = TPB / 2; off >= 1; off >>= 1) {
                if (tid < off) red[tid] += red[tid + off];
                __syncthreads();
            }
            if (tid == 0) cand_val[c] = red[0] + bias[s];
            __syncthreads();
        }
        if (tid == 0) {
            for (int c = 0; c < nc; c++) {
                int rank = 0;
                for (int d = 0; d < nc; d++) {
                    if (d == c) continue;
                    if (cand_val[d] > cand_val[c] ||
                        (cand_val[d] == cand_val[c] && cand_idx[d] < cand_idx[c])) rank++;
                }
                cand_sel[c] = (rank < slots) ? 1 : 0;
            }
        }
    } else {
        if (tid == 0) for (int c = 0; c < nc; c++) cand_sel[c] = 1;
    }
    __syncthreads();

#pragma unroll
    for (int j = 0; j < VPT; j++) {
        float v = unmap(ukey[j]);
        float zv = 0.f;
        if (v > mhi) {
            zv = fmaxf(v, 0.f);
            int slot = atomicAdd(&out_cnt, 1);
            g_tidx[b * KSEL + slot] = tid + TPB * j;
            g_tval[b * KSEL + slot] = zv;
        }
        row[tid + TPB * j] = zv;
    }
    __syncthreads();
    if (tid < nc && cand_sel[tid]) {
        float zv = fmaxf(cand_val[tid], 0.f);
        row[cand_idx[tid]] = zv;
        int slot = atomicAdd(&out_cnt, 1);
        g_tidx[b * KSEL + slot] = cand_idx[tid];
        g_tval[b * KSEL + slot] = zv;
    }
}

// ---------------- kernel 5: sparse decode + per-b loss partial ----------------
__global__ __launch_bounds__(384) void decode_kernel(
    const float* __restrict__ Wdec, const float* __restrict__ bdec,
    const float* __restrict__ x, float* __restrict__ xhat)
{
    __shared__ int   sidx[KSEL];
    __shared__ float sval[KSEL];
    __shared__ float red[384];
    const int b = blockIdx.x, tid = threadIdx.x;
    if (tid < KSEL) { sidx[tid] = g_tidx[b * KSEL + tid]; sval[tid] = g_tval[b * KSEL + tid]; }
    __syncthreads();

    const float4* bd4 = (const float4*)bdec;
    float4 acc0 = bd4[tid], acc1 = bd4[tid + 384], acc2 = bd4[tid + 768];
    const float4* W4 = (const float4*)Wdec;
#pragma unroll 4
    for (int j = 0; j < KSEL; j++) {
        float v = sval[j];
        size_t base = (size_t)sidx[j] * (OD / 4);
        float4 w0 = W4[base + tid], w1 = W4[base + tid + 384], w2 = W4[base + tid + 768];
        acc0.x += v * w0.x; acc0.y += v * w0.y; acc0.z += v * w0.z; acc0.w += v * w0.w;
        acc1.x += v * w1.x; acc1.y += v * w1.y; acc1.z += v * w1.z; acc1.w += v * w1.w;
        acc2.x += v * w2.x; acc2.y += v * w2.y; acc2.z += v * w2.z; acc2.w += v * w2.w;
    }
    const float* xr = x + (size_t)b * OD;
    float* xo = xhat + (size_t)b * OD;
    float s = 0.f;
    {
        int c = 4 * tid;
        float4 xv = *(const float4*)&xr[c];
        float dx = acc0.x - xv.x, dy = acc0.y - xv.y, dz = acc0.z - xv.z, dw = acc0.w - xv.w;
        s += dx*dx + dy*dy + dz*dz + dw*dw;
        xo[c] = acc0.x; xo[c+1] = acc0.y; xo[c+2] = acc0.z; xo[c+3] = acc0.w;
    }
    {
        int c = 4 * (tid + 384);
        float4 xv = *(const float4*)&xr[c];
        float dx = acc1.x - xv.x, dy = acc1.y - xv.y, dz = acc1.z - xv.z, dw = acc1.w - xv.w;
        s += dx*dx + dy*dy + dz*dz + dw*dw;
        xo[c] = acc1.x; xo[c+1] = acc1.y; xo[c+2] = acc1.z; xo[c+3] = acc1.w;
    }
    {
        int c = 4 * (tid + 768);
        float4 xv = *(const float4*)&xr[c];
        float dx = acc2.x - xv.x, dy = acc2.y - xv.y, dz = acc2.z - xv.z, dw = acc2.w - xv.w;
        s += dx*dx + dy*dy + dz*dz + dw*dw;
        xo[c] = acc2.x; xo[c+1] = acc2.y; xo[c+2] = acc2.z; xo[c+3] = acc2.w;
    }
    red[tid] = s;
    __syncthreads();
    if (tid < 128) red[tid] += red[tid + 128] + red[tid + 256];
    __syncthreads();
    if (tid < 64) red[tid] += red[tid + 64];
    __syncthreads();
    if (tid < 32) {
        float v = red[tid] + red[tid + 32];
        for (int off = 16; off >= 1; off >>= 1)
            v += __shfl_down_sync(0xffffffffu, v, off);
        if (tid == 0) g_lpart[b] = v;
    }
}

// ---------------- kernel 6: deterministic final loss reduction ----------------
__global__ void loss_kernel(float* __restrict__ out) {
    __shared__ float red[1024];
    int tid = threadIdx.x;
    float s = g_lpart[tid] + g_lpart[tid + 1024] + g_lpart[tid + 2048] + g_lpart[tid + 3072];
    red[tid] = s;
    __syncthreads();
    for (int off = 512; off >= 1; off >>= 1) {
        if (tid < off) red[tid] += red[tid + off];
        __syncthreads();
    }
    if (tid == 0) out[0] = red[0] / 24576.0f;
}

// ---------------- launch ----------------
extern "C" void kernel_launch(void* const* d_in, const int* in_sizes, int n_in,
                              void* d_out, int out_size)
{
    const float* x     = (const float*)d_in[0];
    const float* W_enc = (const float*)d_in[1];
    const float* b_enc = (const float*)d_in[2];
    const float* W_dec = (const float*)d_in[3];
    const float* b_dec = (const float*)d_in[4];

    float* out  = (float*)d_out;
    float* xhat = out + 1;
    float* z    = out + 1 + (size_t)NB * OD;

    cudaFuncSetAttribute(enc_gemm_kernel, cudaFuncAttributeMaxDynamicSharedMemorySize, GEMM_SMEM_HOST);

    {   // 1. A split (fused t-reduce, saves fp32 Xr)
        int total = NB * (KD / 4);
        convertA_kernel<<<(total + 255) / 256, 256>>>(x);
    }
    {   // 2. B split + transpose
        dim3 grid(KD / 32, DSAE / 32);
        convertB_kernel<<<grid, dim3(32, 8)>>>(W_enc);
    }
    {   // 3. encoder GEMM (cluster-of-2 pairs; pair tile 256x256)
        dim3 grid(2 * (NB / 256), DSAE / 256);   // (32, 64)
        enc_gemm_kernel<<<grid, 512, GEMM_SMEM_HOST>>>(b_enc, z);
    }
    {   // 4. TopK + exact boundary refinement + relu scatter
        topk_kernel<<<NB, TPB>>>(z, W_enc, b_enc);
    }
    {   // 5. sparse decode + loss partials
        decode_kernel<<<NB, 384>>>(W_dec, b_dec, x, xhat);
    }
    {   // 6. final loss
        loss_kernel<<<1, 1024>>>(out);
    }
}

// round 10
// speedup vs baseline: 1.6036x; 1.6036x over previous
#include <cuda_runtime.h>
#include <cuda_bf16.h>
#include <cstdint>

// Problem dims (fixed by reference)
#define NB   4096
#define TT   2
#define LL   3
#define DIN  768
#define DSAE 16384
#define KSEL 64
#define KD   (LL*DIN)      // 2304
#define OD   (TT*LL*DIN)   // 4608

// Does this compilation pass have sm_103a/f features (tcgen05)?
#if defined(__CUDA_ARCH__) && (__CUDA_ARCH__ == 1030) && \
    (defined(__CUDA_ARCH_FEAT_SM103_ALL) || defined(__CUDA_ARCH_SPECIFIC__) || defined(__CUDA_ARCH_FAMILY_SPECIFIC__))
#define HAS_TC 1
#else
#define HAS_TC 0
#endif

// ---------------- scratch (static device memory; no allocations) ----------------
__device__ float g_Xr[(size_t)NB*KD];          // fp32 t-reduced x (for refinement)
__device__ __nv_bfloat16 g_Ahi[(size_t)NB*KD];
__device__ __nv_bfloat16 g_Alo[(size_t)NB*KD];
__device__ __nv_bfloat16 g_Bhi[(size_t)DSAE*KD];
__device__ __nv_bfloat16 g_Blo[(size_t)DSAE*KD];
__device__ int   g_tidx[NB*KSEL];
__device__ float g_tval[NB*KSEL];
__device__ float g_lpart[NB];

// ---------------- helpers ----------------
__device__ __forceinline__ uint32_t smem_u32(const void* p) {
    uint32_t a;
    asm("{ .reg .u64 t; cvta.to.shared.u64 t, %1; cvt.u32.u64 %0, t; }" : "=r"(a) : "l"(p));
    return a;
}
__device__ __forceinline__ uint32_t sw128(uint32_t o) { return o ^ ((o >> 3) & 0x70); }
__device__ __forceinline__ void cp16(uint32_t dst, const void* src) {
    asm volatile("cp.async.cg.shared.global [%0], [%1], 16;" :: "r"(dst), "l"(src));
}
__device__ __forceinline__ void split2(float v, unsigned short& h, unsigned short& l) {
    __nv_bfloat16 hb = __float2bfloat16(v);
    __nv_bfloat16 lb = __float2bfloat16(v - __bfloat162float(hb));
    h = *(unsigned short*)&hb; l = *(unsigned short*)&lb;
}
__device__ __forceinline__ int elect_one() {
    uint32_t pred;
    asm volatile("{\n\t.reg .pred p;\n\telect.sync _|p, 0xFFFFFFFF;\n\tselp.b32 %0, 1, 0, p;\n\t}" : "=r"(pred));
    return (int)pred;
}
__device__ __forceinline__ void mbar_init(uint32_t a, uint32_t cnt) {
    asm volatile("mbarrier.init.shared.b64 [%0], %1;" :: "r"(a), "r"(cnt) : "memory");
}
__device__ __forceinline__ void mbar_wait(uint32_t a, uint32_t parity) {
    asm volatile(
        "{\n\t.reg .pred P;\n"
        "WL_%=:\n\t"
        "mbarrier.try_wait.parity.acquire.cta.shared::cta.b64 P, [%0], %1, 0x989680;\n\t"
        "@P bra WD_%=;\n\t"
        "bra WL_%=;\n"
        "WD_%=:\n\t}"
        :: "r"(a), "r"(parity) : "memory");
}
// mma.sync fallback primitives (plain sm_80+ PTX)
__device__ __forceinline__ void ldsm4(uint32_t* r, uint32_t addr) {
    asm volatile("ldmatrix.sync.aligned.m8n8.x4.shared.b16 {%0,%1,%2,%3}, [%4];"
        : "=r"(r[0]), "=r"(r[1]), "=r"(r[2]), "=r"(r[3]) : "r"(addr));
}
__device__ __forceinline__ void mma16816(float* c, const uint32_t* a, const uint32_t* b) {
    asm volatile("mma.sync.aligned.m16n8k16.row.col.f32.bf16.bf16.f32 "
        "{%0,%1,%2,%3}, {%4,%5,%6,%7}, {%8,%9}, {%0,%1,%2,%3};"
        : "+f"(c[0]), "+f"(c[1]), "+f"(c[2]), "+f"(c[3])
        : "r"(a[0]), "r"(a[1]), "r"(a[2]), "r"(a[3]), "r"(b[0]), "r"(b[1]));
}

#define NSTAGES 72                 // 72 chunks of k=32, all 4 planes per stage
#define STAGE_BYTES 49152          // A(hi|lo) 16KB (128 rows) + B(hi|lo) 32KB (256 rows)
#define GEMM_SMEM_FB   (3 * 49152 + 64)

// ---------------- kernel 1: fused t-reduce + fp32 save + 2-way bf16 split of A ----
__global__ void convertA_kernel(const float* __restrict__ x) {
    int i = blockIdx.x * blockDim.x + threadIdx.x;   // float4 index over [4096, 576]
    if (i >= NB * (KD / 4)) return;
    int b = i / (KD / 4), r = i - b * (KD / 4);
    const float4* x4 = (const float4*)x;
    float4 a = x4[(size_t)b * (OD / 4) + r];
    float4 c = x4[(size_t)b * (OD / 4) + (KD / 4) + r];
    float v[4] = {a.x + c.x, a.y + c.y, a.z + c.z, a.w + c.w};
    ((float4*)g_Xr)[i] = make_float4(v[0], v[1], v[2], v[3]);
    unsigned short h[4], l[4];
#pragma unroll
    for (int j = 0; j < 4; j++) split2(v[j], h[j], l[j]);
    ((uint2*)g_Ahi)[i] = make_uint2((unsigned)h[0] | ((unsigned)h[1] << 16), (unsigned)h[2] | ((unsigned)h[3] << 16));
    ((uint2*)g_Alo)[i] = make_uint2((unsigned)l[0] | ((unsigned)l[1] << 16), (unsigned)l[2] | ((unsigned)l[3] << 16));
}

// ---------------- kernel 2: W_enc transpose [K,N]->[N,K] + 2-way bf16 split -------
__global__ void convertB_kernel(const float* __restrict__ W) {
    __shared__ float ts[32][33];
    const int k0 = blockIdx.x * 32, n0 = blockIdx.y * 32;
    const int tx = threadIdx.x, ty = threadIdx.y;    // (32, 8)
#pragma unroll
    for (int j = 0; j < 4; j++)
        ts[ty + 8 * j][tx] = W[(size_t)(k0 + ty + 8 * j) * DSAE + n0 + tx];
    __syncthreads();
#pragma unroll
    for (int j = 0; j < 4; j++) {
        int nr = ty + 8 * j;
        float v = ts[tx][nr];
        unsigned short h, l;
        split2(v, h, l);
        size_t o = (size_t)(n0 + nr) * KD + k0 + tx;
        ((unsigned short*)g_Bhi)[o] = h;
        ((unsigned short*)g_Blo)[o] = l;
    }
}

// ---------------- kernel 3: encoder GEMM (tcgen05 if available, else mma.sync) ----
// C[4096,16384] fp32, split-bf16 3-term. CTA tile 128x256, 256 threads, 2 CTAs/SM.
__global__ __launch_bounds__(256, 2) void enc_gemm_kernel(
    const float* __restrict__ bias, float* __restrict__ C)
{
    extern __shared__ char smem[];
    const uint32_t sbase = smem_u32(smem);
    const int tid = threadIdx.x, wid = tid >> 5, lid = tid & 31;
    const int bm = blockIdx.x * 128, bn = blockIdx.y * 256;

#if HAS_TC
    // ====== tcgen05 path: 128x256 tile, 2-stage pipeline, 2 CTAs per SM ======
    const uint32_t mbar0 = sbase + 2 * STAGE_BYTES;   // full[2] @ +0, free[2] @ +16
    const uint32_t tptr  = mbar0 + 32;
    if (tid == 0) {
#pragma unroll
        for (int i = 0; i < 2; i++) {
            mbar_init(mbar0 + 8u * i, 256);          // full: 256 producer arrivals
            mbar_init(mbar0 + 16 + 8u * i, 1);       // free: 1 commit arrival
        }
    }
    if (wid == 0) {
        asm volatile("tcgen05.alloc.cta_group::1.sync.aligned.shared::cta.b32 [%0], %1;"
                     :: "r"(tptr), "r"(256u) : "memory");
    }
    __syncthreads();
    uint32_t tmem;
    asm volatile("ld.shared.b32 %0, [%1];" : "=r"(tmem) : "r"(tptr));

    // idesc: f32 acc, bf16 x bf16, N=256, M=128
    const uint32_t idesc = (1u << 4) | (1u << 7) | (1u << 10) | ((256u / 8u) << 17) | ((128u / 16u) << 24);
    static __device__ constexpr uint64_t DESC_BASE =
        (uint64_t(2) << 61) | (uint64_t(1) << 46) | (uint64_t(64) << 32) | (uint64_t(1) << 16);
    const int paoff[3] = {0, 4, 0};   // Ahi, Alo, Ahi   (64B = 4 desc units)
    const int pboff[3] = {0, 0, 4};   // Bhi, Bhi, Blo

    auto produce = [&](int w) {
        const int kin = w * 32;
        const uint32_t sb = sbase + (uint32_t)(w & 1) * STAGE_BYTES;
#pragma unroll
        for (int i2 = 0; i2 < 4; i2++) {             // A: 128 rows x (hi 32 | lo 32)
            int q = tid + 256 * i2;                  // 0..1023
            int row = q >> 3, sub = q & 7;
            int p = sub >> 2, c = sub & 3;
            const __nv_bfloat16* Ap = p ? g_Alo : g_Ahi;
            cp16(sb + sw128((uint32_t)((row << 7) | (p << 6) | (c << 4))),
                 Ap + (size_t)(bm + row) * KD + kin + c * 8);
        }
#pragma unroll
        for (int i2 = 0; i2 < 8; i2++) {             // B: 256 rows x (hi 32 | lo 32)
            int q = tid + 256 * i2;                  // 0..2047
            int row = q >> 3, sub = q & 7;
            int p = sub >> 2, c = sub & 3;
            const __nv_bfloat16* Bp = p ? g_Blo : g_Bhi;
            cp16(sb + 16384u + sw128((uint32_t)((row << 7) | (p << 6) | (c << 4))),
                 Bp + (size_t)(bn + row) * KD + kin + c * 8);
        }
        asm volatile("cp.async.mbarrier.arrive.noinc.shared::cta.b64 [%0];"
                     :: "r"(mbar0 + 8u * (uint32_t)(w & 1)) : "memory");
    };

    produce(0); produce(1);

    for (int s = 0; s < NSTAGES; s++) {
        const int buf = s & 1;
        const uint32_t fullb = mbar0 + 8u * (uint32_t)buf;
        const uint32_t freeb = mbar0 + 16u + 8u * (uint32_t)buf;
        const int u = s >> 1;

        if (wid == 0 && elect_one()) {
            mbar_wait(fullb, (uint32_t)(u & 1));
            asm volatile("fence.proxy.async.shared::cta;" ::: "memory");
            const uint32_t sb = sbase + (uint32_t)buf * STAGE_BYTES;
            uint64_t ad = DESC_BASE | ((uint64_t)(sb >> 4) & 0x3FFF);
            uint64_t bd = DESC_BASE | ((uint64_t)((sb + 16384u) >> 4) & 0x3FFF);
#pragma unroll
            for (int combo = 0; combo < 3; combo++) {
#pragma unroll
                for (int ks = 0; ks < 2; ks++) {
                    uint32_t en = ((s > 0) || (combo > 0) || (ks > 0)) ? 1u : 0u;
                    asm volatile(
                        "{\n\t.reg .pred p;\n\t"
                        "setp.ne.u32 p, %4, 0;\n\t"
                        "tcgen05.mma.cta_group::1.kind::f16 [%0], %1, %2, %3, {%5, %5, %5, %5}, p;\n\t}"
                        :: "r"(tmem), "l"(ad + paoff[combo] + ks * 2),
                           "l"(bd + pboff[combo] + ks * 2), "r"(idesc), "r"(en), "r"(0u)
                        : "memory");
                }
            }
            asm volatile("tcgen05.commit.cta_group::1.mbarrier::arrive::one.shared::cluster.b64 [%0];"
                         :: "r"(freeb) : "memory");
        }

        const int w = s + 2;
        if (w < NSTAGES) {
            mbar_wait(freeb, (uint32_t)(((w >> 1) - 1) & 1));
            produce(w);
        }
    }

    // drain: buf0 last commit usage 35, buf1 usage 35 -> parity 1
    mbar_wait(mbar0 + 16u, 1u);
    mbar_wait(mbar0 + 24u, 1u);
    asm volatile("tcgen05.fence::after_thread_sync;" ::: "memory");
    __syncthreads();

    // epilogue: 8 warps; sp = wid&3 (32 rows), half = wid>>2 (128 cols)
    {
        const int sp = wid & 3, half = wid >> 2;
        const int m = sp * 32 + lid;
        const size_t crow = (size_t)(bm + m) * DSAE + bn + half * 128;
#pragma unroll
        for (int cb = 0; cb < 128; cb += 32) {
            uint32_t r[32];
            asm volatile(
                "tcgen05.ld.sync.aligned.32x32b.x32.b32 "
                "{%0, %1, %2, %3, %4, %5, %6, %7, %8, %9, %10, %11, %12, %13, %14, %15, "
                "%16, %17, %18, %19, %20, %21, %22, %23, %24, %25, %26, %27, %28, %29, %30, %31}, [%32];"
                : "=r"(r[0]), "=r"(r[1]), "=r"(r[2]), "=r"(r[3]), "=r"(r[4]), "=r"(r[5]), "=r"(r[6]), "=r"(r[7]),
                  "=r"(r[8]), "=r"(r[9]), "=r"(r[10]), "=r"(r[11]), "=r"(r[12]), "=r"(r[13]), "=r"(r[14]), "=r"(r[15]),
                  "=r"(r[16]), "=r"(r[17]), "=r"(r[18]), "=r"(r[19]), "=r"(r[20]), "=r"(r[21]), "=r"(r[22]), "=r"(r[23]),
                  "=r"(r[24]), "=r"(r[25]), "=r"(r[26]), "=r"(r[27]), "=r"(r[28]), "=r"(r[29]), "=r"(r[30]), "=r"(r[31])
                : "r"(tmem + (uint32_t)(half * 128 + cb)));
            asm volatile("tcgen05.wait::ld.sync.aligned;" ::: "memory");
#pragma unroll
            for (int j = 0; j < 32; j++)
                C[crow + cb + j] = __uint_as_float(r[j]) + __ldg(&bias[bn + half * 128 + cb + j]);
        }
    }
    asm volatile("tcgen05.fence::before_thread_sync;" ::: "memory");
    __syncthreads();
    if (wid == 0) {
        asm volatile("tcgen05.relinquish_alloc_permit.cta_group::1.sync.aligned;" ::: "memory");
        asm volatile("tcgen05.dealloc.cta_group::1.sync.aligned.b32 %0, %1;" :: "r"(tmem), "r"(256u));
    }
#else
    // ================= mma.sync fallback (plain sm_103) =================
    const int wm = (wid & 3) * 32;
    const int wn = (wid >> 2) * 64;

    for (int nh = 0; nh < 2; nh++) {
        float acc[2][8][4];
#pragma unroll
        for (int mi = 0; mi < 2; mi++)
#pragma unroll
            for (int j = 0; j < 8; j++)
#pragma unroll
                for (int e = 0; e < 4; e++) acc[mi][j][e] = 0.f;

        auto load_stage_f = [&](int w) {
            int kin = w * 32;
            uint32_t sb = sbase + (uint32_t)(w % 3) * STAGE_BYTES;
#pragma unroll
            for (int i2 = 0; i2 < 4; i2++) {        // A: 128 rows x (hi|lo)
                int q = tid + 256 * i2;
                int row = q >> 3, sub = q & 7;
                int p = sub >> 2, c = sub & 3;
                const __nv_bfloat16* Ap = p ? g_Alo : g_Ahi;
                cp16(sb + sw128((uint32_t)((row << 7) | (p << 6) | (c << 4))),
                     Ap + (size_t)(bm + row) * KD + kin + c * 8);
            }
#pragma unroll
            for (int i2 = 0; i2 < 4; i2++) {        // B half: 128 rows x (hi|lo)
                int q = tid + 256 * i2;
                int row = q >> 3, sub = q & 7;
                int p = sub >> 2, c = sub & 3;
                const __nv_bfloat16* Bp = p ? g_Blo : g_Bhi;
                cp16(sb + 16384u + sw128((uint32_t)((row << 7) | (p << 6) | (c << 4))),
                     Bp + (size_t)(bn + nh * 128 + row) * KD + kin + c * 8);
            }
            asm volatile("cp.async.commit_group;" ::: "memory");
        };

        load_stage_f(0);
        load_stage_f(1);

        for (int s = 0; s < NSTAGES; s++) {
            if (s + 2 < NSTAGES) {
                load_stage_f(s + 2);
                asm volatile("cp.async.wait_group 2;" ::: "memory");
            } else if (s == NSTAGES - 2) {
                asm volatile("cp.async.wait_group 1;" ::: "memory");
            } else {
                asm volatile("cp.async.wait_group 0;" ::: "memory");
            }
            __syncthreads();
            uint32_t ab = sbase + (uint32_t)(s % 3) * STAGE_BYTES;
            uint32_t bb = ab + 16384u;
            const int paoff[3] = {0, 64, 0};
            const int pboff[3] = {0, 0, 64};
#pragma unroll
            for (int combo = 0; combo < 3; combo++) {
#pragma unroll
                for (int ks = 0; ks < 2; ks++) {
                    uint32_t a[2][4];
#pragma unroll
                    for (int mi = 0; mi < 2; mi++) {
                        int row = wm + mi * 16 + (lid & 15);
                        uint32_t addr = ab + sw128((uint32_t)(row * 128 + paoff[combo] + ks * 32 + (lid >> 4) * 16));
                        ldsm4(a[mi], addr);
                    }
                    uint32_t bq[8][2];
#pragma unroll
                    for (int nj = 0; nj < 4; nj++) {
                        int mat = lid >> 3, rin = lid & 7;
                        int n = wn + nj * 16 + ((mat >> 1) << 3) + rin;
                        int kb = pboff[combo] + ks * 32 + ((mat & 1) << 4);
                        uint32_t r4[4];
                        ldsm4(r4, bb + sw128((uint32_t)(n * 128 + kb)));
                        bq[nj * 2][0] = r4[0]; bq[nj * 2][1] = r4[1];
                        bq[nj * 2 + 1][0] = r4[2]; bq[nj * 2 + 1][1] = r4[3];
                    }
#pragma unroll
                    for (int mi = 0; mi < 2; mi++)
#pragma unroll
                        for (int j = 0; j < 8; j++) mma16816(acc[mi][j], a[mi], bq[j]);
                }
            }
            __syncthreads();
        }

#pragma unroll
        for (int mi = 0; mi < 2; mi++)
#pragma unroll
            for (int j = 0; j < 8; j++) {
                int col = bn + nh * 128 + wn + j * 8 + (lid & 3) * 2;
                float b0v = __ldg(&bias[col]), b1v = __ldg(&bias[col + 1]);
                int r0 = bm + wm + mi * 16 + (lid >> 2);
                C[(size_t)r0 * DSAE + col]           = acc[mi][j][0] + b0v;
                C[(size_t)r0 * DSAE + col + 1]       = acc[mi][j][1] + b1v;
                C[(size_t)(r0 + 8) * DSAE + col]     = acc[mi][j][2] + b0v;
                C[(size_t)(r0 + 8) * DSAE + col + 1] = acc[mi][j][3] + b1v;
            }
        __syncthreads();
    }
#endif
}

// ---------------- kernel 4: TopK-64, register-resident + exact boundary refine ----
#define MARGIN 1e-3f
#define TPB 1024
#define VPT (DSAE / TPB)     // 16 values per thread
__global__ __launch_bounds__(TPB, 1) void topk_kernel(
    float* __restrict__ zbase,
    const float* __restrict__ Wenc,
    const float* __restrict__ bias)
{
    __shared__ int hist[4096];
    __shared__ int wsum[32];
    __shared__ float red[TPB];
    __shared__ int sh_B, sh_rem;
    __shared__ int n_hi, n_cand, out_cnt;
    __shared__ int   cand_idx[64];
    __shared__ float cand_val[64];
    __shared__ unsigned char cand_sel[64];

    const int b = blockIdx.x;
    const int tid = threadIdx.x;
    const int lane = tid & 31, warp = tid >> 5;
    float* row = zbase + (size_t)b * DSAE;

    unsigned ukey[VPT];
#pragma unroll
    for (int j = 0; j < VPT; j++) {
        unsigned u = __float_as_uint(row[tid + TPB * j]);
        ukey[j] = (u & 0x80000000u) ? ~u : (u | 0x80000000u);
    }

    int B1 = 0, target = KSEL;
#pragma unroll 1
    for (int pass = 0; pass < 2; pass++) {
#pragma unroll
        for (int i = tid; i < 4096; i += TPB) hist[i] = 0;
        __syncthreads();
#pragma unroll
        for (int j = 0; j < VPT; j++) {
            unsigned u = ukey[j];
            if (pass == 0) atomicAdd(&hist[u >> 20], 1);
            else if ((int)(u >> 20) == B1) atomicAdd(&hist[(u >> 8) & 0xFFFu], 1);
        }
        __syncthreads();
        int base = 4095 - 4 * tid;
        int s0 = hist[base] + hist[base - 1] + hist[base - 2] + hist[base - 3];
        int v = s0;
#pragma unroll
        for (int off = 1; off < 32; off <<= 1) {
            int n = __shfl_up_sync(0xffffffffu, v, off);
            if (lane >= off) v += n;
        }
        if (lane == 31) wsum[warp] = v;
        __syncthreads();
        if (warp == 0) {
            int t = wsum[lane];
#pragma unroll
            for (int off = 1; off < 32; off <<= 1) {
                int n = __shfl_up_sync(0xffffffffu, t, off);
                if (lane >= off) t += n;
            }
            wsum[lane] = t;
        }
        __syncthreads();
        int incl = v + (warp ? wsum[warp - 1] : 0);
        int excl = incl - s0;
        if (excl < target && target <= incl) {
            int rem = target - excl;
            for (int k = 0; k < 4; k++) {
                int bin = base - k;
                int c = hist[bin];
                if (c >= rem) { sh_B = bin; sh_rem = rem; break; }
                rem -= c;
            }
        }
        __syncthreads();
        if (pass == 0) { B1 = sh_B; target = sh_rem; }
        __syncthreads();
    }
    const unsigned P = ((unsigned)B1 << 12) | (unsigned)sh_B;

    auto unmap = [](unsigned u) {
        return __uint_as_float((u & 0x80000000u) ? (u & 0x7fffffffu) : ~u);
    };
    const float TL = unmap(P << 8);
    const float TH = unmap((P + 1) << 8);
    const float mlo = fminf(TL, TH) - MARGIN;
    const float mhi = fmaxf(TL, TH) + MARGIN;

    if (tid == 0) { n_hi = 0; n_cand = 0; out_cnt = 0; }
    __syncthreads();

#pragma unroll
    for (int j = 0; j < VPT; j++) {
        float v = unmap(ukey[j]);
        if (v > mhi) atomicAdd(&n_hi, 1);
        else if (v > mlo) {
            int e = atomicAdd(&n_cand, 1);
            if (e < 64) { cand_idx[e] = tid + TPB * j; cand_val[e] = v; }
        }
    }
    __syncthreads();
    const int slots = KSEL - n_hi;
    const int nc = (n_cand < 64) ? n_cand : 64;

    if (nc > slots) {
        for (int c = 0; c < nc; c++) {
            int s = cand_idx[c];
            float partial = 0.f;
            const float* xr = g_Xr + (size_t)b * KD;
            for (int k = tid; k < KD; k += TPB)
                partial += xr[k] * Wenc[(size_t)k * DSAE + s];
            red[tid] = partial;
            __syncthreads();
            for (int off = TPB / 2; off >= 1; off >>= 1) {
                if (tid < off) red[tid] += red[tid + off];
                __syncthreads();
            }
            if (tid == 0) cand_val[c] = red[0] + bias[s];
            __syncthreads();
        }
        if (tid == 0) {
            for (int c = 0; c < nc; c++) {
                int rank = 0;
                for (int d = 0; d < nc; d++) {
                    if (d == c) continue;
                    if (cand_val[d] > cand_val[c] ||
                        (cand_val[d] == cand_val[c] && cand_idx[d] < cand_idx[c])) rank++;
                }
                cand_sel[c] = (rank < slots) ? 1 : 0;
            }
        }
    } else {
        if (tid == 0) for (int c = 0; c < nc; c++) cand_sel[c] = 1;
    }
    __syncthreads();

#pragma unroll
    for (int j = 0; j < VPT; j++) {
        float v = unmap(ukey[j]);
        float zv = 0.f;
        if (v > mhi) {
            zv = fmaxf(v, 0.f);
            int slot = atomicAdd(&out_cnt, 1);
            g_tidx[b * KSEL + slot] = tid + TPB * j;
            g_tval[b * KSEL + slot] = zv;
        }
        row[tid + TPB * j] = zv;
    }
    __syncthreads();
    if (tid < nc && cand_sel[tid]) {
        float zv = fmaxf(cand_val[tid], 0.f);
        row[cand_idx[tid]] = zv;
        int slot = atomicAdd(&out_cnt, 1);
        g_tidx[b * KSEL + slot] = cand_idx[tid];
        g_tval[b * KSEL + slot] = zv;
    }
}

// ---------------- kernel 5: sparse decode + per-b loss partial ----------------
__global__ __launch_bounds__(384) void decode_kernel(
    const float* __restrict__ Wdec, const float* __restrict__ bdec,
    const float* __restrict__ x, float* __restrict__ xhat)
{
    __shared__ int   sidx[KSEL];
    __shared__ float sval[KSEL];
    __shared__ float red[384];
    const int b = blockIdx.x, tid = threadIdx.x;
    if (tid < KSEL) { sidx[tid] = g_tidx[b * KSEL + tid]; sval[tid] = g_tval[b * KSEL + tid]; }
    __syncthreads();

    const float4* bd4 = (const float4*)bdec;
    float4 acc0 = bd4[tid], acc1 = bd4[tid + 384], acc2 = bd4[tid + 768];
    const float4* W4 = (const float4*)Wdec;
#pragma unroll 4
    for (int j = 0; j < KSEL; j++) {
        float v = sval[j];
        size_t base = (size_t)sidx[j] * (OD / 4);
        float4 w0 = W4[base + tid], w1 = W4[base + tid + 384], w2 = W4[base + tid + 768];
        acc0.x += v * w0.x; acc0.y += v * w0.y; acc0.z += v * w0.z; acc0.w += v * w0.w;
        acc1.x += v * w1.x; acc1.y += v * w1.y; acc1.z += v * w1.z; acc1.w += v * w1.w;
        acc2.x += v * w2.x; acc2.y += v * w2.y; acc2.z += v * w2.z; acc2.w += v * w2.w;
    }
    const float* xr = x + (size_t)b * OD;
    float* xo = xhat + (size_t)b * OD;
    float s = 0.f;
    {
        int c = 4 * tid;
        float4 xv = *(const float4*)&xr[c];
        float dx = acc0.x - xv.x, dy = acc0.y - xv.y, dz = acc0.z - xv.z, dw = acc0.w - xv.w;
        s += dx*dx + dy*dy + dz*dz + dw*dw;
        xo[c] = acc0.x; xo[c+1] = acc0.y; xo[c+2] = acc0.z; xo[c+3] = acc0.w;
    }
    {
        int c = 4 * (tid + 384);
        float4 xv = *(const float4*)&xr[c];
        float dx = acc1.x - xv.x, dy = acc1.y - xv.y, dz = acc1.z - xv.z, dw = acc1.w - xv.w;
        s += dx*dx + dy*dy + dz*dz + dw*dw;
        xo[c] = acc1.x; xo[c+1] = acc1.y; xo[c+2] = acc1.z; xo[c+3] = acc1.w;
    }
    {
        int c = 4 * (tid + 768);
        float4 xv = *(const float4*)&xr[c];
        float dx = acc2.x - xv.x, dy = acc2.y - xv.y, dz = acc2.z - xv.z, dw = acc2.w - xv.w;
        s += dx*dx + dy*dy + dz*dz + dw*dw;
        xo[c] = acc2.x; xo[c+1] = acc2.y; xo[c+2] = acc2.z; xo[c+3] = acc2.w;
    }
    red[tid] = s;
    __syncthreads();
    if (tid < 128) red[tid] += red[tid + 128] + red[tid + 256];
    __syncthreads();
    if (tid < 64) red[tid] += red[tid + 64];
    __syncthreads();
    if (tid < 32) {
        float v = red[tid] + red[tid + 32];
        for (int off = 16; off >= 1; off >>= 1)
            v += __shfl_down_sync(0xffffffffu, v, off);
        if (tid == 0) g_lpart[b] = v;
    }
}

// ---------------- kernel 6: deterministic final loss reduction ----------------
__global__ void loss_kernel(float* __restrict__ out) {
    __shared__ float red[1024];
    int tid = threadIdx.x;
    float s = g_lpart[tid] + g_lpart[tid + 1024] + g_lpart[tid + 2048] + g_lpart[tid + 3072];
    red[tid] = s;
    __syncthreads();
    for (int off = 512; off >= 1; off >>= 1) {
        if (tid < off) red[tid] += red[tid + off];
        __syncthreads();
    }
    if (tid == 0) out[0] = red[0] / 24576.0f;
}

// ---------------- launch ----------------
extern "C" void kernel_launch(void* const* d_in, const int* in_sizes, int n_in,
                              void* d_out, int out_size)
{
    const float* x     = (const float*)d_in[0];
    const float* W_enc = (const float*)d_in[1];
    const float* b_enc = (const float*)d_in[2];
    const float* W_dec = (const float*)d_in[3];
    const float* b_dec = (const float*)d_in[4];

    float* out  = (float*)d_out;
    float* xhat = out + 1;
    float* z    = out + 1 + (size_t)NB * OD;

    cudaFuncSetAttribute(enc_gemm_kernel, cudaFuncAttributeMaxDynamicSharedMemorySize, GEMM_SMEM_FB);

    {   // 1. A split (fused t-reduce, saves fp32 Xr)
        int total = NB * (KD / 4);
        convertA_kernel<<<(total + 255) / 256, 256>>>(x);
    }
    {   // 2. B split + transpose
        dim3 grid(KD / 32, DSAE / 32);
        convertB_kernel<<<grid, dim3(32, 8)>>>(W_enc);
    }
    {   // 3. encoder GEMM -> pre written into z region (128x256 tiles, 2 CTAs/SM)
        dim3 grid(NB / 128, DSAE / 256);
        enc_gemm_kernel<<<grid, 256, 2 * STAGE_BYTES + 64>>>(b_enc, z);
    }
    {   // 4. TopK + exact boundary refinement + relu scatter
        topk_kernel<<<NB, TPB>>>(z, W_enc, b_enc);
    }
    {   // 5. sparse decode + loss partials
        decode_kernel<<<NB, 384>>>(W_dec, b_dec, x, xhat);
    }
    {   // 6. final loss
        loss_kernel<<<1, 1024>>>(out);
    }
}

// round 11
// speedup vs baseline: 2.0679x; 1.2895x over previous
#include <cuda_runtime.h>
#include <cuda_bf16.h>
#include <cstdint>

// Problem dims (fixed by reference)
#define NB   4096
#define TT   2
#define LL   3
#define DIN  768
#define DSAE 16384
#define KSEL 64
#define KD   (LL*DIN)      // 2304
#define OD   (TT*LL*DIN)   // 4608

// Does this compilation pass have sm_103a/f features (tcgen05)?
#if defined(__CUDA_ARCH__) && (__CUDA_ARCH__ == 1030) && \
    (defined(__CUDA_ARCH_FEAT_SM103_ALL) || defined(__CUDA_ARCH_SPECIFIC__) || defined(__CUDA_ARCH_FAMILY_SPECIFIC__))
#define HAS_TC 1
#else
#define HAS_TC 0
#endif

// ---------------- scratch (static device memory; no allocations) ----------------
__device__ float g_Xr[(size_t)NB*KD];          // fp32 t-reduced x (for refinement)
__device__ __nv_bfloat16 g_Ahi[(size_t)NB*KD];
__device__ __nv_bfloat16 g_Alo[(size_t)NB*KD];
__device__ __nv_bfloat16 g_Bhi[(size_t)DSAE*KD];
__device__ __nv_bfloat16 g_Blo[(size_t)DSAE*KD];
__device__ int   g_tidx[NB*KSEL];
__device__ float g_tval[NB*KSEL];
__device__ float g_lpart[NB];

// ---------------- helpers ----------------
__device__ __forceinline__ uint32_t smem_u32(const void* p) {
    uint32_t a;
    asm("{ .reg .u64 t; cvta.to.shared.u64 t, %1; cvt.u32.u64 %0, t; }" : "=r"(a) : "l"(p));
    return a;
}
__device__ __forceinline__ uint32_t sw128(uint32_t o) { return o ^ ((o >> 3) & 0x70); }
__device__ __forceinline__ void cp16(uint32_t dst, const void* src) {
    asm volatile("cp.async.cg.shared.global [%0], [%1], 16;" :: "r"(dst), "l"(src));
}
__device__ __forceinline__ void split2(float v, unsigned short& h, unsigned short& l) {
    __nv_bfloat16 hb = __float2bfloat16(v);
    __nv_bfloat16 lb = __float2bfloat16(v - __bfloat162float(hb));
    h = *(unsigned short*)&hb; l = *(unsigned short*)&lb;
}
__device__ __forceinline__ int elect_one() {
    uint32_t pred;
    asm volatile("{\n\t.reg .pred p;\n\telect.sync _|p, 0xFFFFFFFF;\n\tselp.b32 %0, 1, 0, p;\n\t}" : "=r"(pred));
    return (int)pred;
}
__device__ __forceinline__ void mbar_init(uint32_t a, uint32_t cnt) {
    asm volatile("mbarrier.init.shared.b64 [%0], %1;" :: "r"(a), "r"(cnt) : "memory");
}
__device__ __forceinline__ void mbar_wait(uint32_t a, uint32_t parity) {
    asm volatile(
        "{\n\t.reg .pred P;\n"
        "WL_%=:\n\t"
        "mbarrier.try_wait.parity.acquire.cta.shared::cta.b64 P, [%0], %1, 0x989680;\n\t"
        "@P bra WD_%=;\n\t"
        "bra WL_%=;\n"
        "WD_%=:\n\t}"
        :: "r"(a), "r"(parity) : "memory");
}
// mma.sync fallback primitives (plain sm_80+ PTX)
__device__ __forceinline__ void ldsm4(uint32_t* r, uint32_t addr) {
    asm volatile("ldmatrix.sync.aligned.m8n8.x4.shared.b16 {%0,%1,%2,%3}, [%4];"
        : "=r"(r[0]), "=r"(r[1]), "=r"(r[2]), "=r"(r[3]) : "r"(addr));
}
__device__ __forceinline__ void mma16816(float* c, const uint32_t* a, const uint32_t* b) {
    asm volatile("mma.sync.aligned.m16n8k16.row.col.f32.bf16.bf16.f32 "
        "{%0,%1,%2,%3}, {%4,%5,%6,%7}, {%8,%9}, {%0,%1,%2,%3};"
        : "+f"(c[0]), "+f"(c[1]), "+f"(c[2]), "+f"(c[3])
        : "r"(a[0]), "r"(a[1]), "r"(a[2]), "r"(a[3]), "r"(b[0]), "r"(b[1]));
}

#define NSTAGES 72                 // 72 chunks of k=32, all 4 planes per stage
#if HAS_TC
#define STAGE_BYTES 65536          // A(hi|lo) 32KB (2 atoms) + B(hi|lo) 32KB
#else
#define STAGE_BYTES 49152
#endif
#define GEMM_SMEM_HOST (3 * 65536 + 128)

// ---------------- kernel 1: fused t-reduce + fp32 save + 2-way bf16 split of A ----
__global__ void convertA_kernel(const float* __restrict__ x) {
    int i = blockIdx.x * blockDim.x + threadIdx.x;   // float4 index over [4096, 576]
    if (i >= NB * (KD / 4)) return;
    int b = i / (KD / 4), r = i - b * (KD / 4);
    const float4* x4 = (const float4*)x;
    float4 a = x4[(size_t)b * (OD / 4) + r];
    float4 c = x4[(size_t)b * (OD / 4) + (KD / 4) + r];
    float v[4] = {a.x + c.x, a.y + c.y, a.z + c.z, a.w + c.w};
    ((float4*)g_Xr)[i] = make_float4(v[0], v[1], v[2], v[3]);
    unsigned short h[4], l[4];
#pragma unroll
    for (int j = 0; j < 4; j++) split2(v[j], h[j], l[j]);
    ((uint2*)g_Ahi)[i] = make_uint2((unsigned)h[0] | ((unsigned)h[1] << 16), (unsigned)h[2] | ((unsigned)h[3] << 16));
    ((uint2*)g_Alo)[i] = make_uint2((unsigned)l[0] | ((unsigned)l[1] << 16), (unsigned)l[2] | ((unsigned)l[3] << 16));
}

// ---------------- kernel 2: W_enc transpose [K,N]->[N,K] + 2-way bf16 split -------
__global__ void convertB_kernel(const float* __restrict__ W) {
    __shared__ float ts[32][33];
    const int k0 = blockIdx.x * 32, n0 = blockIdx.y * 32;
    const int tx = threadIdx.x, ty = threadIdx.y;    // (32, 8)
#pragma unroll
    for (int j = 0; j < 4; j++)
        ts[ty + 8 * j][tx] = W[(size_t)(k0 + ty + 8 * j) * DSAE + n0 + tx];
    __syncthreads();
#pragma unroll
    for (int j = 0; j < 4; j++) {
        int nr = ty + 8 * j;
        float v = ts[tx][nr];
        unsigned short h, l;
        split2(v, h, l);
        size_t o = (size_t)(n0 + nr) * KD + k0 + tx;
        ((unsigned short*)g_Bhi)[o] = h;
        ((unsigned short*)g_Blo)[o] = l;
    }
}

// ---------------- kernel 3: encoder GEMM (tcgen05 if available, else mma.sync) ----
// C[4096,16384] fp32, split-bf16 3-term. CTA tile 256x256, 512 threads.
// WARP-SPECIALIZED: warp 0 = MMA consumer (never waits on MMA completion),
// warps 8-15 = cp.async producers (gated on free barriers), 3-deep pipeline.
__global__ __launch_bounds__(512, 1) void enc_gemm_kernel(
    const float* __restrict__ bias, float* __restrict__ C)
{
    extern __shared__ char smem[];
    const uint32_t sbase = smem_u32(smem);
    const int tid = threadIdx.x, wid = tid >> 5, lid = tid & 31;
    const int bm = blockIdx.x * 256, bn = blockIdx.y * 256;

#if HAS_TC
    // layout: full[3] @ mbar0, free[3] @ +24, done @ +48, tmem ptr @ +56
    const uint32_t mbar0 = sbase + 3 * STAGE_BYTES;
    const uint32_t doneb = mbar0 + 48;
    const uint32_t tptr  = mbar0 + 56;
    if (tid == 0) {
#pragma unroll
        for (int i = 0; i < 3; i++) {
            mbar_init(mbar0 + 8u * i, 256);          // full: 256 producer arrivals
            mbar_init(mbar0 + 24 + 8u * i, 1);       // free: 1 commit arrival
        }
        mbar_init(doneb, 1);                         // final drain barrier
    }
    if (wid == 0) {
        asm volatile("tcgen05.alloc.cta_group::1.sync.aligned.shared::cta.b32 [%0], %1;"
                     :: "r"(tptr), "r"(512u) : "memory");
    }
    __syncthreads();
    uint32_t tmem;
    asm volatile("ld.shared.b32 %0, [%1];" : "=r"(tmem) : "r"(tptr));

    // idesc: f32 acc, bf16 x bf16, N=256, M=128
    const uint32_t idesc = (1u << 4) | (1u << 7) | (1u << 10) | ((256u / 8u) << 17) | ((128u / 16u) << 24);
    static __device__ constexpr uint64_t DESC_BASE =
        (uint64_t(2) << 61) | (uint64_t(1) << 46) | (uint64_t(64) << 32) | (uint64_t(1) << 16);
    const int paoff[3] = {0, 4, 0};   // Ahi, Alo, Ahi   (64B = 4 desc units)
    const int pboff[3] = {0, 0, 4};   // Bhi, Bhi, Blo

    if (wid == 0) {
        // ================= consumer: issue MMAs, never wait for completion ========
        if (elect_one()) {
            for (int s = 0; s < NSTAGES; s++) {
                const int buf = s % 3;
                mbar_wait(mbar0 + 8u * (uint32_t)buf, (uint32_t)((s / 3) & 1));
                asm volatile("fence.proxy.async.shared::cta;" ::: "memory");
                const uint32_t sb = sbase + (uint32_t)buf * STAGE_BYTES;
                uint64_t ad = DESC_BASE | ((uint64_t)(sb >> 4) & 0x3FFF);
                uint64_t bd = DESC_BASE | ((uint64_t)((sb + 32768u) >> 4) & 0x3FFF);
#pragma unroll
                for (int combo = 0; combo < 3; combo++) {
#pragma unroll
                    for (int ks = 0; ks < 2; ks++) {
                        uint32_t en = ((s > 0) || (combo > 0) || (ks > 0)) ? 1u : 0u;
                        uint64_t a0 = ad + paoff[combo] + ks * 2;
                        uint64_t b0 = bd + pboff[combo] + ks * 2;
                        asm volatile(
                            "{\n\t.reg .pred p;\n\t"
                            "setp.ne.u32 p, %4, 0;\n\t"
                            "tcgen05.mma.cta_group::1.kind::f16 [%0], %1, %2, %3, {%5, %5, %5, %5}, p;\n\t}"
                            :: "r"(tmem), "l"(a0), "l"(b0), "r"(idesc), "r"(en), "r"(0u) : "memory");
                        asm volatile(
                            "{\n\t.reg .pred p;\n\t"
                            "setp.ne.u32 p, %4, 0;\n\t"
                            "tcgen05.mma.cta_group::1.kind::f16 [%0], %1, %2, %3, {%5, %5, %5, %5}, p;\n\t}"
                            :: "r"(tmem + 256u), "l"(a0 + 1024), "l"(b0), "r"(idesc), "r"(en), "r"(0u) : "memory");
                    }
                }
                asm volatile("tcgen05.commit.cta_group::1.mbarrier::arrive::one.shared::cluster.b64 [%0];"
                             :: "r"(mbar0 + 24u + 8u * (uint32_t)buf) : "memory");
            }
            // final drain marker: arrives when ALL prior MMAs complete
            asm volatile("tcgen05.commit.cta_group::1.mbarrier::arrive::one.shared::cluster.b64 [%0];"
                         :: "r"(doneb) : "memory");
        }
    } else if (wid >= 8) {
        // ================= producers: warps 8-15, 256 threads, 16 cp16/stage ======
        const int ptid = tid - 256;
        for (int w = 0; w < NSTAGES; w++) {
            const int buf = w % 3;
            if (w >= 3)
                mbar_wait(mbar0 + 24u + 8u * (uint32_t)buf, (uint32_t)(((w / 3) - 1) & 1));
            const int kin = w * 32;
            const uint32_t sb = sbase + (uint32_t)buf * STAGE_BYTES;
#pragma unroll
            for (int i2 = 0; i2 < 8; i2++) {         // A: 256 rows x (hi 32 | lo 32)
                int q = ptid + 256 * i2;             // 0..2047
                int row = q >> 3, sub = q & 7;
                int p = sub >> 2, c = sub & 3;
                const __nv_bfloat16* Ap = p ? g_Alo : g_Ahi;
                uint32_t off = (uint32_t)(((row & 127) << 7) | (p << 6) | (c << 4));
                cp16(sb + ((uint32_t)(row >> 7) << 14) + sw128(off),
                     Ap + (size_t)(bm + row) * KD + kin + c * 8);
            }
#pragma unroll
            for (int i2 = 0; i2 < 8; i2++) {         // B: 256 rows x (hi 32 | lo 32)
                int q = ptid + 256 * i2;
                int row = q >> 3, sub = q & 7;
                int p = sub >> 2, c = sub & 3;
                const __nv_bfloat16* Bp = p ? g_Blo : g_Bhi;
                uint32_t off = (uint32_t)((row << 7) | (p << 6) | (c << 4));
                cp16(sb + 32768u + sw128(off),
                     Bp + (size_t)(bn + row) * KD + kin + c * 8);
            }
            asm volatile("cp.async.mbarrier.arrive.noinc.shared::cta.b64 [%0];"
                         :: "r"(mbar0 + 8u * (uint32_t)buf) : "memory");
        }
    }

    // everyone converges on the single-phase done barrier (ABA-safe)
    mbar_wait(doneb, 0u);
    asm volatile("tcgen05.fence::after_thread_sync;" ::: "memory");
    __syncthreads();

    // epilogue: 16 warps; atom = wid>>3 (M-half), cg = (wid>>2)&1 (N-half), sp = wid&3
    {
        const int sp = wid & 3, cg = (wid >> 2) & 1, atom = wid >> 3;
        const int m = atom * 128 + sp * 32 + lid;
        const size_t crow = (size_t)(bm + m) * DSAE + bn + cg * 128;
        const uint32_t tbase = tmem + (uint32_t)(atom * 256 + cg * 128);
#pragma unroll
        for (int cb = 0; cb < 128; cb += 32) {
            uint32_t r[32];
            asm volatile(
                "tcgen05.ld.sync.aligned.32x32b.x32.b32 "
                "{%0, %1, %2, %3, %4, %5, %6, %7, %8, %9, %10, %11, %12, %13, %14, %15, "
                "%16, %17, %18, %19, %20, %21, %22, %23, %24, %25, %26, %27, %28, %29, %30, %31}, [%32];"
                : "=r"(r[0]), "=r"(r[1]), "=r"(r[2]), "=r"(r[3]), "=r"(r[4]), "=r"(r[5]), "=r"(r[6]), "=r"(r[7]),
                  "=r"(r[8]), "=r"(r[9]), "=r"(r[10]), "=r"(r[11]), "=r"(r[12]), "=r"(r[13]), "=r"(r[14]), "=r"(r[15]),
                  "=r"(r[16]), "=r"(r[17]), "=r"(r[18]), "=r"(r[19]), "=r"(r[20]), "=r"(r[21]), "=r"(r[22]), "=r"(r[23]),
                  "=r"(r[24]), "=r"(r[25]), "=r"(r[26]), "=r"(r[27]), "=r"(r[28]), "=r"(r[29]), "=r"(r[30]), "=r"(r[31])
                : "r"(tbase + (uint32_t)cb));
            asm volatile("tcgen05.wait::ld.sync.aligned;" ::: "memory");
#pragma unroll
            for (int j = 0; j < 32; j++)
                C[crow + cb + j] = __uint_as_float(r[j]) + __ldg(&bias[bn + cg * 128 + cb + j]);
        }
    }
    asm volatile("tcgen05.fence::before_thread_sync;" ::: "memory");
    __syncthreads();
    if (wid == 0) {
        asm volatile("tcgen05.relinquish_alloc_permit.cta_group::1.sync.aligned;" ::: "memory");
        asm volatile("tcgen05.dealloc.cta_group::1.sync.aligned.b32 %0, %1;" :: "r"(tmem), "r"(512u));
    }
#else
    // ================= mma.sync fallback (plain sm_103) =================
    // 16 warps, warp tile 32x64 over a 128x256 subtile; two M-half passes.
    const int wm = (wid & 3) * 32;
    const int wn = (wid >> 2) * 64;

    for (int mh = 0; mh < 2; mh++) {
        const int bme = bm + mh * 128;
        float acc[2][8][4];
#pragma unroll
        for (int mi = 0; mi < 2; mi++)
#pragma unroll
            for (int j = 0; j < 8; j++)
#pragma unroll
                for (int e = 0; e < 4; e++) acc[mi][j][e] = 0.f;

        auto load_stage_f = [&](int w) {
            int kin = w * 32;
            uint32_t sb = sbase + (uint32_t)(w % 3) * STAGE_BYTES;
#pragma unroll
            for (int i2 = 0; i2 < 2; i2++) {        // A: 128 rows x (hi|lo)
                int q = tid + 512 * i2;
                int row = q >> 3, sub = q & 7;
                int p = sub >> 2, c = sub & 3;
                const __nv_bfloat16* Ap = p ? g_Alo : g_Ahi;
                cp16(sb + sw128((uint32_t)((row << 7) | (p << 6) | (c << 4))),
                     Ap + (size_t)(bme + row) * KD + kin + c * 8);
            }
#pragma unroll
            for (int i2 = 0; i2 < 4; i2++) {        // B: 256 rows x (hi|lo)
                int q = tid + 512 * i2;
                int row = q >> 3, sub = q & 7;
                int p = sub >> 2, c = sub & 3;
                const __nv_bfloat16* Bp = p ? g_Blo : g_Bhi;
                cp16(sb + 16384u + sw128((uint32_t)((row << 7) | (p << 6) | (c << 4))),
                     Bp + (size_t)(bn + row) * KD + kin + c * 8);
            }
            asm volatile("cp.async.commit_group;" ::: "memory");
        };

        load_stage_f(0);
        load_stage_f(1);

        for (int s = 0; s < NSTAGES; s++) {
            if (s + 2 < NSTAGES) {
                load_stage_f(s + 2);
                asm volatile("cp.async.wait_group 2;" ::: "memory");
            } else if (s == NSTAGES - 2) {
                asm volatile("cp.async.wait_group 1;" ::: "memory");
            } else {
                asm volatile("cp.async.wait_group 0;" ::: "memory");
            }
            __syncthreads();
            uint32_t ab = sbase + (uint32_t)(s % 3) * STAGE_BYTES;
            uint32_t bb = ab + 16384u;
            const int paoff2[3] = {0, 64, 0};
            const int pboff2[3] = {0, 0, 64};
#pragma unroll
            for (int combo = 0; combo < 3; combo++) {
#pragma unroll
                for (int ks = 0; ks < 2; ks++) {
                    uint32_t a[2][4];
#pragma unroll
                    for (int mi = 0; mi < 2; mi++) {
                        int row = wm + mi * 16 + (lid & 15);
                        uint32_t addr = ab + sw128((uint32_t)(row * 128 + paoff2[combo] + ks * 32 + (lid >> 4) * 16));
                        ldsm4(a[mi], addr);
                    }
                    uint32_t bq[8][2];
#pragma unroll
                    for (int nj = 0; nj < 4; nj++) {
                        int mat = lid >> 3, rin = lid & 7;
                        int n = wn + nj * 16 + ((mat >> 1) << 3) + rin;
                        int kb = pboff2[combo] + ks * 32 + ((mat & 1) << 4);
                        uint32_t r4[4];
                        ldsm4(r4, bb + sw128((uint32_t)(n * 128 + kb)));
                        bq[nj * 2][0] = r4[0]; bq[nj * 2][1] = r4[1];
                        bq[nj * 2 + 1][0] = r4[2]; bq[nj * 2 + 1][1] = r4[3];
                    }
#pragma unroll
                    for (int mi = 0; mi < 2; mi++)
#pragma unroll
                        for (int j = 0; j < 8; j++) mma16816(acc[mi][j], a[mi], bq[j]);
                }
            }
            __syncthreads();
        }

#pragma unroll
        for (int mi = 0; mi < 2; mi++)
#pragma unroll
            for (int j = 0; j < 8; j++) {
                int col = bn + wn + j * 8 + (lid & 3) * 2;
                float b0v = __ldg(&bias[col]), b1v = __ldg(&bias[col + 1]);
                int r0 = bme + wm + mi * 16 + (lid >> 2);
                C[(size_t)r0 * DSAE + col]           = acc[mi][j][0] + b0v;
                C[(size_t)r0 * DSAE + col + 1]       = acc[mi][j][1] + b1v;
                C[(size_t)(r0 + 8) * DSAE + col]     = acc[mi][j][2] + b0v;
                C[(size_t)(r0 + 8) * DSAE + col + 1] = acc[mi][j][3] + b1v;
            }
        __syncthreads();
    }
#endif
}

// ---------------- kernel 4: TopK-64, register-resident + exact boundary refine ----
#define MARGIN 1e-3f
#define TPB 1024
#define VPT (DSAE / TPB)     // 16 values per thread
__global__ __launch_bounds__(TPB, 1) void topk_kernel(
    float* __restrict__ zbase,
    const float* __restrict__ Wenc,
    const float* __restrict__ bias)
{
    __shared__ int hist[4096];
    __shared__ int wsum[32];
    __shared__ float red[TPB];
    __shared__ int sh_B, sh_rem;
    __shared__ int n_hi, n_cand, out_cnt;
    __shared__ int   cand_idx[64];
    __shared__ float cand_val[64];
    __shared__ unsigned char cand_sel[64];

    const int b = blockIdx.x;
    const int tid = threadIdx.x;
    const int lane = tid & 31, warp = tid >> 5;
    float* row = zbase + (size_t)b * DSAE;

    unsigned ukey[VPT];
#pragma unroll
    for (int j = 0; j < VPT; j++) {
        unsigned u = __float_as_uint(row[tid + TPB * j]);
        ukey[j] = (u & 0x80000000u) ? ~u : (u | 0x80000000u);
    }

    int B1 = 0, target = KSEL;
#pragma unroll 1
    for (int pass = 0; pass < 2; pass++) {
#pragma unroll
        for (int i = tid; i < 4096; i += TPB) hist[i] = 0;
        __syncthreads();
#pragma unroll
        for (int j = 0; j < VPT; j++) {
            unsigned u = ukey[j];
            if (pass == 0) atomicAdd(&hist[u >> 20], 1);
            else if ((int)(u >> 20) == B1) atomicAdd(&hist[(u >> 8) & 0xFFFu], 1);
        }
        __syncthreads();
        int base = 4095 - 4 * tid;
        int s0 = hist[base] + hist[base - 1] + hist[base - 2] + hist[base - 3];
        int v = s0;
#pragma unroll
        for (int off = 1; off < 32; off <<= 1) {
            int n = __shfl_up_sync(0xffffffffu, v, off);
            if (lane >= off) v += n;
        }
        if (lane == 31) wsum[warp] = v;
        __syncthreads();
        if (warp == 0) {
            int t = wsum[lane];
#pragma unroll
            for (int off = 1; off < 32; off <<= 1) {
                int n = __shfl_up_sync(0xffffffffu, t, off);
                if (lane >= off) t += n;
            }
            wsum[lane] = t;
        }
        __syncthreads();
        int incl = v + (warp ? wsum[warp - 1] : 0);
        int excl = incl - s0;
        if (excl < target && target <= incl) {
            int rem = target - excl;
            for (int k = 0; k < 4; k++) {
                int bin = base - k;
                int c = hist[bin];
                if (c >= rem) { sh_B = bin; sh_rem = rem; break; }
                rem -= c;
            }
        }
        __syncthreads();
        if (pass == 0) { B1 = sh_B; target = sh_rem; }
        __syncthreads();
    }
    const unsigned P = ((unsigned)B1 << 12) | (unsigned)sh_B;

    auto unmap = [](unsigned u) {
        return __uint_as_float((u & 0x80000000u) ? (u & 0x7fffffffu) : ~u);
    };
    const float TL = unmap(P << 8);
    const float TH = unmap((P + 1) << 8);
    const float mlo = fminf(TL, TH) - MARGIN;
    const float mhi = fmaxf(TL, TH) + MARGIN;

    if (tid == 0) { n_hi = 0; n_cand = 0; out_cnt = 0; }
    __syncthreads();

#pragma unroll
    for (int j = 0; j < VPT; j++) {
        float v = unmap(ukey[j]);
        if (v > mhi) atomicAdd(&n_hi, 1);
        else if (v > mlo) {
            int e = atomicAdd(&n_cand, 1);
            if (e < 64) { cand_idx[e] = tid + TPB * j; cand_val[e] = v; }
        }
    }
    __syncthreads();
    const int slots = KSEL - n_hi;
    const int nc = (n_cand < 64) ? n_cand : 64;

    if (nc > slots) {
        for (int c = 0; c < nc; c++) {
            int s = cand_idx[c];
            float partial = 0.f;
            const float* xr = g_Xr + (size_t)b * KD;
            for (int k = tid; k < KD; k += TPB)
                partial += xr[k] * Wenc[(size_t)k * DSAE + s];
            red[tid] = partial;
            __syncthreads();
            for (int off = TPB / 2; off >= 1; off >>= 1) {
                if (tid < off) red[tid] += red[tid + off];
                __syncthreads();
            }
            if (tid == 0) cand_val[c] = red[0] + bias[s];
            __syncthreads();
        }
        if (tid == 0) {
            for (int c = 0; c < nc; c++) {
                int rank = 0;
                for (int d = 0; d < nc; d++) {
                    if (d == c) continue;
                    if (cand_val[d] > cand_val[c] ||
                        (cand_val[d] == cand_val[c] && cand_idx[d] < cand_idx[c])) rank++;
                }
                cand_sel[c] = (rank < slots) ? 1 : 0;
            }
        }
    } else {
        if (tid == 0) for (int c = 0; c < nc; c++) cand_sel[c] = 1;
    }
    __syncthreads();

#pragma unroll
    for (int j = 0; j < VPT; j++) {
        float v = unmap(ukey[j]);
        float zv = 0.f;
        if (v > mhi) {
            zv = fmaxf(v, 0.f);
            int slot = atomicAdd(&out_cnt, 1);
            g_tidx[b * KSEL + slot] = tid + TPB * j;
            g_tval[b * KSEL + slot] = zv;
        }
        row[tid + TPB * j] = zv;
    }
    __syncthreads();
    if (tid < nc && cand_sel[tid]) {
        float zv = fmaxf(cand_val[tid], 0.f);
        row[cand_idx[tid]] = zv;
        int slot = atomicAdd(&out_cnt, 1);
        g_tidx[b * KSEL + slot] = cand_idx[tid];
        g_tval[b * KSEL + slot] = zv;
    }
}

// ---------------- kernel 5: sparse decode + per-b loss partial ----------------
__global__ __launch_bounds__(384) void decode_kernel(
    const float* __restrict__ Wdec, const float* __restrict__ bdec,
    const float* __restrict__ x, float* __restrict__ xhat)
{
    __shared__ int   sidx[KSEL];
    __shared__ float sval[KSEL];
    __shared__ float red[384];
    const int b = blockIdx.x, tid = threadIdx.x;
    if (tid < KSEL) { sidx[tid] = g_tidx[b * KSEL + tid]; sval[tid] = g_tval[b * KSEL + tid]; }
    __syncthreads();

    const float4* bd4 = (const float4*)bdec;
    float4 acc0 = bd4[tid], acc1 = bd4[tid + 384], acc2 = bd4[tid + 768];
    const float4* W4 = (const float4*)Wdec;
#pragma unroll 4
    for (int j = 0; j < KSEL; j++) {
        float v = sval[j];
        size_t base = (size_t)sidx[j] * (OD / 4);
        float4 w0 = W4[base + tid], w1 = W4[base + tid + 384], w2 = W4[base + tid + 768];
        acc0.x += v * w0.x; acc0.y += v * w0.y; acc0.z += v * w0.z; acc0.w += v * w0.w;
        acc1.x += v * w1.x; acc1.y += v * w1.y; acc1.z += v * w1.z; acc1.w += v * w1.w;
        acc2.x += v * w2.x; acc2.y += v * w2.y; acc2.z += v * w2.z; acc2.w += v * w2.w;
    }
    const float* xr = x + (size_t)b * OD;
    float* xo = xhat + (size_t)b * OD;
    float s = 0.f;
    {
        int c = 4 * tid;
        float4 xv = *(const float4*)&xr[c];
        float dx = acc0.x - xv.x, dy = acc0.y - xv.y, dz = acc0.z - xv.z, dw = acc0.w - xv.w;
        s += dx*dx + dy*dy + dz*dz + dw*dw;
        xo[c] = acc0.x; xo[c+1] = acc0.y; xo[c+2] = acc0.z; xo[c+3] = acc0.w;
    }
    {
        int c = 4 * (tid + 384);
        float4 xv = *(const float4*)&xr[c];
        float dx = acc1.x - xv.x, dy = acc1.y - xv.y, dz = acc1.z - xv.z, dw = acc1.w - xv.w;
        s += dx*dx + dy*dy + dz*dz + dw*dw;
        xo[c] = acc1.x; xo[c+1] = acc1.y; xo[c+2] = acc1.z; xo[c+3] = acc1.w;
    }
    {
        int c = 4 * (tid + 768);
        float4 xv = *(const float4*)&xr[c];
        float dx = acc2.x - xv.x, dy = acc2.y - xv.y, dz = acc2.z - xv.z, dw = acc2.w - xv.w;
        s += dx*dx + dy*dy + dz*dz + dw*dw;
        xo[c] = acc2.x; xo[c+1] = acc2.y; xo[c+2] = acc2.z; xo[c+3] = acc2.w;
    }
    red[tid] = s;
    __syncthreads();
    if (tid < 128) red[tid] += red[tid + 128] + red[tid + 256];
    __syncthreads();
    if (tid < 64) red[tid] += red[tid + 64];
    __syncthreads();
    if (tid < 32) {
        float v = red[tid] + red[tid + 32];
        for (int off = 16; off >= 1; off >>= 1)
            v += __shfl_down_sync(0xffffffffu, v, off);
        if (tid == 0) g_lpart[b] = v;
    }
}

// ---------------- kernel 6: deterministic final loss reduction ----------------
__global__ void loss_kernel(float* __restrict__ out) {
    __shared__ float red[1024];
    int tid = threadIdx.x;
    float s = g_lpart[tid] + g_lpart[tid + 1024] + g_lpart[tid + 2048] + g_lpart[tid + 3072];
    red[tid] = s;
    __syncthreads();
    for (int off = 512; off >= 1; off >>= 1) {
        if (tid < off) red[tid] += red[tid + off];
        __syncthreads();
    }
    if (tid == 0) out[0] = red[0] / 24576.0f;
}

// ---------------- launch ----------------
extern "C" void kernel_launch(void* const* d_in, const int* in_sizes, int n_in,
                              void* d_out, int out_size)
{
    const float* x     = (const float*)d_in[0];
    const float* W_enc = (const float*)d_in[1];
    const float* b_enc = (const float*)d_in[2];
    const float* W_dec = (const float*)d_in[3];
    const float* b_dec = (const float*)d_in[4];

    float* out  = (float*)d_out;
    float* xhat = out + 1;
    float* z    = out + 1 + (size_t)NB * OD;

    cudaFuncSetAttribute(enc_gemm_kernel, cudaFuncAttributeMaxDynamicSharedMemorySize, GEMM_SMEM_HOST);

    {   // 1. A split (fused t-reduce, saves fp32 Xr)
        int total = NB * (KD / 4);
        convertA_kernel<<<(total + 255) / 256, 256>>>(x);
    }
    {   // 2. B split + transpose
        dim3 grid(KD / 32, DSAE / 32);
        convertB_kernel<<<grid, dim3(32, 8)>>>(W_enc);
    }
    {   // 3. encoder GEMM -> pre written into z region (warp-specialized pipeline)
        dim3 grid(NB / 256, DSAE / 256);
        enc_gemm_kernel<<<grid, 512, GEMM_SMEM_HOST>>>(b_enc, z);
    }
    {   // 4. TopK + exact boundary refinement + relu scatter
        topk_kernel<<<NB, TPB>>>(z, W_enc, b_enc);
    }
    {   // 5. sparse decode + loss partials
        decode_kernel<<<NB, 384>>>(W_dec, b_dec, x, xhat);
    }
    {   // 6. final loss
        loss_kernel<<<1, 1024>>>(out);
    }
}